// round 1
// baseline (speedup 1.0000x reference)
#include <cuda_runtime.h>

// ---------------------------------------------------------------------------
// att0_26_2layer: fully-fused 2-layer GAT-style attention, one CTA per batch.
//
// Math trick: exp(leaky_relu(q+k)) = max(e^q * e^k, e^{.01q} * e^{.01k})
// so all exps hoist out of the O(B*N*N*D) inner loop.
// ---------------------------------------------------------------------------

#define TPB 512

constexpr int Bn = 512;
constexpr int Nn = 50;
constexpr int Dn = 64;
constexpr int ND = Nn * Dn;                 // 3200
constexpr int EMB_STRIDE = (Nn + 1) * Dn;   // 3264

// shared memory layout (floats)
constexpr int O_X   = 0;            // x, later av1 (layer-2 input)
constexpr int O_UI  = ND;           // ui = emb[:,0,:] * i_em
constexpr int O_ATT = 2 * ND;       // raw attention output (att1, then att2)
constexpr int O_EQ  = 3 * ND;
constexpr int O_FQ  = 4 * ND;
constexpr int O_EK  = 5 * ND;
constexpr int O_FK  = 6 * ND;
constexpr int O_WA1 = 7 * ND;
constexpr int O_WA2 = O_WA1 + Dn * Dn;
constexpr int O_W1  = O_WA2 + Dn * Dn;
constexpr int O_W2  = O_W1  + Dn * Dn;
constexpr int O_BA1 = O_W2  + Dn * Dn;
constexpr int O_BA2 = O_BA1 + Dn;
constexpr int O_B1  = O_BA2 + Dn;
constexpr int O_B2  = O_B1  + Dn;
constexpr int SMEM_FLOATS = O_B2 + Dn;      // 39040 floats = 156160 bytes

// q = in@Wa1 + ba1, k = in@Wa2 + ba2; store Eq,Fq,Ek,Fk = exp{q,.01q,k,.01k}
// Input is always sm[O_X] (x for layer 1, av1 for layer 2).
__device__ __forceinline__ void qk_phase(float* sm) {
    const int tid = threadIdx.x;
    const int d4  = (tid & 15) << 2;   // 4-wide column group
    const int g   = tid >> 4;          // 0..31 row group
#pragma unroll
    for (int p = 0; p < 2; ++p) {
        const int i  = g + 32 * p;
        const int ii = (i < Nn) ? i : (Nn - 1);
        const float* __restrict__ xr = sm + O_X + ii * Dn;
        float aq0 = 0.f, aq1 = 0.f, aq2 = 0.f, aq3 = 0.f;
        float ak0 = 0.f, ak1 = 0.f, ak2 = 0.f, ak3 = 0.f;
#pragma unroll 16
        for (int c = 0; c < Dn; ++c) {
            const float xv = xr[c];
            const float4 a = *reinterpret_cast<const float4*>(sm + O_WA1 + c * Dn + d4);
            const float4 bb = *reinterpret_cast<const float4*>(sm + O_WA2 + c * Dn + d4);
            aq0 = fmaf(xv, a.x, aq0);  aq1 = fmaf(xv, a.y, aq1);
            aq2 = fmaf(xv, a.z, aq2);  aq3 = fmaf(xv, a.w, aq3);
            ak0 = fmaf(xv, bb.x, ak0); ak1 = fmaf(xv, bb.y, ak1);
            ak2 = fmaf(xv, bb.z, ak2); ak3 = fmaf(xv, bb.w, ak3);
        }
        if (i < Nn) {
            const float q0 = aq0 + sm[O_BA1 + d4 + 0];
            const float q1 = aq1 + sm[O_BA1 + d4 + 1];
            const float q2 = aq2 + sm[O_BA1 + d4 + 2];
            const float q3 = aq3 + sm[O_BA1 + d4 + 3];
            const float k0 = ak0 + sm[O_BA2 + d4 + 0];
            const float k1 = ak1 + sm[O_BA2 + d4 + 1];
            const float k2 = ak2 + sm[O_BA2 + d4 + 2];
            const float k3 = ak3 + sm[O_BA2 + d4 + 3];
            float4 v;
            v = make_float4(__expf(q0), __expf(q1), __expf(q2), __expf(q3));
            *reinterpret_cast<float4*>(sm + O_EQ + i * Dn + d4) = v;
            v = make_float4(__expf(0.01f*q0), __expf(0.01f*q1), __expf(0.01f*q2), __expf(0.01f*q3));
            *reinterpret_cast<float4*>(sm + O_FQ + i * Dn + d4) = v;
            v = make_float4(__expf(k0), __expf(k1), __expf(k2), __expf(k3));
            *reinterpret_cast<float4*>(sm + O_EK + i * Dn + d4) = v;
            v = make_float4(__expf(0.01f*k0), __expf(0.01f*k1), __expf(0.01f*k2), __expf(0.01f*k3));
            *reinterpret_cast<float4*>(sm + O_FK + i * Dn + d4) = v;
        }
    }
}

// att[i,d] = (sum_j max(Eq_i*Ek_j, Fq_i*Fk_j) * x_j) / (sum_j max(...))
// Value array is sm[O_X] (x for layer 1, av1 for layer 2). Output -> sm[O_ATT].
__device__ __forceinline__ void att_phase(float* sm) {
    const int tid = threadIdx.x;
    const int d = tid & 63;
    const int g = tid >> 6;   // 0..7
    float eq[7], fq[7], num[7], den[7];
#pragma unroll
    for (int r = 0; r < 7; ++r) {
        const int i  = g + 8 * r;
        const int ii = (i < Nn) ? i : (Nn - 1);
        eq[r] = sm[O_EQ + ii * Dn + d];
        fq[r] = sm[O_FQ + ii * Dn + d];
        num[r] = 0.f;
        den[r] = 0.f;
    }
#pragma unroll 5
    for (int j = 0; j < Nn; ++j) {
        const float ek = sm[O_EK + j * Dn + d];
        const float fk = sm[O_FK + j * Dn + d];
        const float xv = sm[O_X  + j * Dn + d];
#pragma unroll
        for (int r = 0; r < 7; ++r) {
            const float w = fmaxf(eq[r] * ek, fq[r] * fk);
            den[r] += w;
            num[r] = fmaf(w, xv, num[r]);
        }
    }
#pragma unroll
    for (int r = 0; r < 7; ++r) {
        const int i = g + 8 * r;
        if (i < Nn) sm[O_ATT + i * Dn + d] = __fdividef(num[r], den[r]);
    }
}

// FINAL=false: sm[O_X] = sm[O_ATT] @ W1 + b1            (av1, layer-2 input)
// FINAL=true : out     = lrelu(ui + av1 + sm[O_ATT]@W2 + b2)
template <bool FINAL>
__device__ __forceinline__ void gemm_att(float* sm, int wofs, int bofs,
                                         float* __restrict__ out, int b) {
    const int tid = threadIdx.x;
    const int d4  = (tid & 15) << 2;
    const int g   = tid >> 4;
#pragma unroll
    for (int p = 0; p < 2; ++p) {
        const int i  = g + 32 * p;
        const int ii = (i < Nn) ? i : (Nn - 1);
        const float* __restrict__ ar = sm + O_ATT + ii * Dn;
        float a0 = 0.f, a1 = 0.f, a2 = 0.f, a3 = 0.f;
#pragma unroll 16
        for (int c = 0; c < Dn; ++c) {
            const float xv = ar[c];
            const float4 w = *reinterpret_cast<const float4*>(sm + wofs + c * Dn + d4);
            a0 = fmaf(xv, w.x, a0); a1 = fmaf(xv, w.y, a1);
            a2 = fmaf(xv, w.z, a2); a3 = fmaf(xv, w.w, a3);
        }
        if (i < Nn) {
            float t0 = a0 + sm[bofs + d4 + 0];
            float t1 = a1 + sm[bofs + d4 + 1];
            float t2 = a2 + sm[bofs + d4 + 2];
            float t3 = a3 + sm[bofs + d4 + 3];
            if (!FINAL) {
                *reinterpret_cast<float4*>(sm + O_X + i * Dn + d4) =
                    make_float4(t0, t1, t2, t3);
            } else {
                t0 += sm[O_X + i * Dn + d4 + 0] + sm[O_UI + i * Dn + d4 + 0];
                t1 += sm[O_X + i * Dn + d4 + 1] + sm[O_UI + i * Dn + d4 + 1];
                t2 += sm[O_X + i * Dn + d4 + 2] + sm[O_UI + i * Dn + d4 + 2];
                t3 += sm[O_X + i * Dn + d4 + 3] + sm[O_UI + i * Dn + d4 + 3];
                const float4 o = make_float4(fmaxf(t0, 0.01f * t0),
                                             fmaxf(t1, 0.01f * t1),
                                             fmaxf(t2, 0.01f * t2),
                                             fmaxf(t3, 0.01f * t3));
                *reinterpret_cast<float4*>(out + b * ND + i * Dn + d4) = o;
            }
        }
    }
}

__global__ void __launch_bounds__(TPB, 1)
att0_fused_kernel(const float* __restrict__ emb,
                  const float* __restrict__ Wa1, const float* __restrict__ ba1,
                  const float* __restrict__ Wa2, const float* __restrict__ ba2,
                  const float* __restrict__ W1,  const float* __restrict__ b1,
                  const float* __restrict__ W2,  const float* __restrict__ b2,
                  float* __restrict__ out) {
    extern __shared__ float sm[];
    const int b   = blockIdx.x;
    const int tid = threadIdx.x;
    const float* __restrict__ eb = emb + b * EMB_STRIDE;

    // load x = i_em[b], ui = emb[b,0,:] * x, all weights + biases
    for (int idx = tid; idx < ND; idx += TPB) {
        const float v = eb[Dn + idx];
        sm[O_X + idx]  = v;
        sm[O_UI + idx] = v * __ldg(eb + (idx & (Dn - 1)));
    }
    for (int idx = tid; idx < Dn * Dn; idx += TPB) {
        sm[O_WA1 + idx] = Wa1[idx];
        sm[O_WA2 + idx] = Wa2[idx];
        sm[O_W1  + idx] = W1[idx];
        sm[O_W2  + idx] = W2[idx];
    }
    if (tid < Dn) {
        sm[O_BA1 + tid] = ba1[tid];
        sm[O_BA2 + tid] = ba2[tid];
        sm[O_B1  + tid] = b1[tid];
        sm[O_B2  + tid] = b2[tid];
    }
    __syncthreads();

    // ---- layer 1 ----
    qk_phase(sm);                                   __syncthreads();
    att_phase(sm);                                  __syncthreads();
    gemm_att<false>(sm, O_W1, O_B1, out, b);        __syncthreads();  // av1 -> O_X
    // ---- layer 2 ----
    qk_phase(sm);                                   __syncthreads();
    att_phase(sm);                                  __syncthreads();
    // out = lrelu(ui + av1 + att2@W2 + b2)
    gemm_att<true>(sm, O_W2, O_B2, out, b);
}

extern "C" void kernel_launch(void* const* d_in, const int* in_sizes, int n_in,
                              void* d_out, int out_size) {
    const float* emb = (const float*)d_in[0];
    const float* Wa1 = (const float*)d_in[1];
    const float* ba1 = (const float*)d_in[2];
    const float* Wa2 = (const float*)d_in[3];
    const float* ba2 = (const float*)d_in[4];
    const float* W1  = (const float*)d_in[5];
    const float* b1  = (const float*)d_in[6];
    const float* W2  = (const float*)d_in[7];
    const float* b2  = (const float*)d_in[8];
    float* out = (float*)d_out;

    const size_t smem = SMEM_FLOATS * sizeof(float);   // 156160 B
    cudaFuncSetAttribute(att0_fused_kernel,
                         cudaFuncAttributeMaxDynamicSharedMemorySize, (int)smem);
    att0_fused_kernel<<<Bn, TPB, smem>>>(emb, Wa1, ba1, Wa2, ba2, W1, b1, W2, b2, out);
}

// round 2
// speedup vs baseline: 1.4910x; 1.4910x over previous
#include <cuda_runtime.h>

// ---------------------------------------------------------------------------
// Fully-fused 2-layer GAT attention. 512 CTAs x 256 threads, 2 CTAs/SM.
// exp(leaky_relu(q+k)) = max(e^q e^k, e^{.01q} e^{.01k})  -> no exp in O(N^2 D).
// All hot math uses packed f32x2 (2 fp32 lanes per fma-pipe instruction).
// N x D arrays padded to row stride 68 to break 32-way bank conflicts.
// ---------------------------------------------------------------------------

#define TPB 256
typedef unsigned long long u64;

constexpr int Bn = 512;
constexpr int Nn = 50;
constexpr int Dn = 64;
constexpr int STR = 68;                       // padded row stride (floats)
constexpr int EMB_STRIDE = (Nn + 1) * Dn;     // 3264

// shared layout (floats)
constexpr int O_X   = 0;                       // x / av1   (50*68)
constexpr int O_EQ  = Nn * STR;                // Eq, later ATT (aliased)
constexpr int O_FQ  = 2 * Nn * STR;
constexpr int O_EK  = 3 * Nn * STR;            // Ek; doubles as W-scratch in gemm
constexpr int O_FK  = 4 * Nn * STR;
constexpr int O_WS  = O_EK;                    // 4096-float W scratch (EK+FK dead)
constexpr int O_WA1 = 5 * Nn * STR;            // 17000
constexpr int O_WA2 = O_WA1 + Dn * Dn;
constexpr int O_BA1 = O_WA2 + Dn * Dn;         // 25192
constexpr int O_BA2 = O_BA1 + Dn;
constexpr int O_B1  = O_BA2 + Dn;
constexpr int O_B2  = O_B1 + Dn;
constexpr int O_E0  = O_B2 + Dn;
constexpr int SMEM_FLOATS = O_E0 + Dn;         // 25512 -> 102048 B

// ---- f32x2 helpers --------------------------------------------------------
__device__ __forceinline__ u64 pk2(float lo, float hi) {
    u64 r; asm("mov.b64 %0, {%1,%2};" : "=l"(r) : "f"(lo), "f"(hi)); return r;
}
__device__ __forceinline__ float lo32(u64 v) {
    float a, b; asm("mov.b64 {%0,%1}, %2;" : "=f"(a), "=f"(b) : "l"(v)); return a;
}
__device__ __forceinline__ float hi32(u64 v) {
    float a, b; asm("mov.b64 {%0,%1}, %2;" : "=f"(a), "=f"(b) : "l"(v)); return b;
}
__device__ __forceinline__ u64 fma2(u64 a, u64 b, u64 c) {
    u64 d; asm("fma.rn.f32x2 %0, %1, %2, %3;" : "=l"(d) : "l"(a), "l"(b), "l"(c)); return d;
}
__device__ __forceinline__ u64 mul2(u64 a, u64 b) {
    u64 d; asm("mul.rn.f32x2 %0, %1, %2;" : "=l"(d) : "l"(a), "l"(b)); return d;
}
__device__ __forceinline__ u64 add2(u64 a, u64 b) {
    u64 d; asm("add.rn.f32x2 %0, %1, %2;" : "=l"(d) : "l"(a), "l"(b)); return d;
}
__device__ __forceinline__ u64 max2(u64 a, u64 b) {   // per-half fmax (alu pipe)
    float al, ah, bl, bh;
    asm("mov.b64 {%0,%1}, %2;" : "=f"(al), "=f"(ah) : "l"(a));
    asm("mov.b64 {%0,%1}, %2;" : "=f"(bl), "=f"(bh) : "l"(b));
    return pk2(fmaxf(al, bl), fmaxf(ah, bh));
}

// ---- qk: q = x@Wa1+ba1, k = x@Wa2+ba2 -> Eq,Fq,Ek,Fk ------------------------
__device__ __forceinline__ void qk_phase(float* sm) {
    const int tid  = threadIdx.x;
    const int lane = tid & 31;
    const int w    = tid >> 5;        // 0..7
    const int cg   = w & 3;           // 4 col groups of 16
    const int rg   = w >> 2;          // 2 row groups of 32
    const int row  = rg * 32 + lane;  // 0..63
    const int rr   = (row < Nn) ? row : (Nn - 1);
    const int col0 = cg * 16;

    u64 aq[8], ak[8];
#pragma unroll
    for (int k = 0; k < 8; ++k) { aq[k] = 0ull; ak[k] = 0ull; }

    const float* __restrict__ xrow = sm + O_X + rr * STR;
#pragma unroll
    for (int c0 = 0; c0 < Dn; c0 += 8) {
        const float4 xa = *reinterpret_cast<const float4*>(xrow + c0);
        const float4 xb = *reinterpret_cast<const float4*>(xrow + c0 + 4);
        const float xs[8] = {xa.x, xa.y, xa.z, xa.w, xb.x, xb.y, xb.z, xb.w};
#pragma unroll
        for (int u = 0; u < 8; ++u) {
            const int c = c0 + u;
            const u64 xx = pk2(xs[u], xs[u]);
            const ulonglong2* __restrict__ wa =
                reinterpret_cast<const ulonglong2*>(sm + O_WA1 + c * Dn + col0);
            const ulonglong2* __restrict__ wb =
                reinterpret_cast<const ulonglong2*>(sm + O_WA2 + c * Dn + col0);
#pragma unroll
            for (int t = 0; t < 4; ++t) {
                const ulonglong2 A = wa[t];
                const ulonglong2 B = wb[t];
                aq[2 * t]     = fma2(xx, A.x, aq[2 * t]);
                aq[2 * t + 1] = fma2(xx, A.y, aq[2 * t + 1]);
                ak[2 * t]     = fma2(xx, B.x, ak[2 * t]);
                ak[2 * t + 1] = fma2(xx, B.y, ak[2 * t + 1]);
            }
        }
    }
    if (row < Nn) {
        const int base = row * STR + col0;
#pragma unroll
        for (int t = 0; t < 4; ++t) {
            const u64 q0 = add2(aq[2 * t],     *reinterpret_cast<const u64*>(sm + O_BA1 + col0 + 4 * t));
            const u64 q1 = add2(aq[2 * t + 1], *reinterpret_cast<const u64*>(sm + O_BA1 + col0 + 4 * t + 2));
            const u64 k0 = add2(ak[2 * t],     *reinterpret_cast<const u64*>(sm + O_BA2 + col0 + 4 * t));
            const u64 k1 = add2(ak[2 * t + 1], *reinterpret_cast<const u64*>(sm + O_BA2 + col0 + 4 * t + 2));
            const float qa = lo32(q0), qb = hi32(q0), qc = lo32(q1), qd = hi32(q1);
            const float ka = lo32(k0), kb = hi32(k0), kc = lo32(k1), kd = hi32(k1);
            *reinterpret_cast<float4*>(sm + O_EQ + base + 4 * t) =
                make_float4(__expf(qa), __expf(qb), __expf(qc), __expf(qd));
            *reinterpret_cast<float4*>(sm + O_FQ + base + 4 * t) =
                make_float4(__expf(0.01f * qa), __expf(0.01f * qb),
                            __expf(0.01f * qc), __expf(0.01f * qd));
            *reinterpret_cast<float4*>(sm + O_EK + base + 4 * t) =
                make_float4(__expf(ka), __expf(kb), __expf(kc), __expf(kd));
            *reinterpret_cast<float4*>(sm + O_FK + base + 4 * t) =
                make_float4(__expf(0.01f * ka), __expf(0.01f * kb),
                            __expf(0.01f * kc), __expf(0.01f * kd));
        }
    }
}

// ---- attention: ATT[i,d] = sum_j max(EqEk,FqFk)*x[j,d] / sum_j max(...) -----
// ATT written back into the EQ region (same (i,d) slots this thread read).
__device__ __forceinline__ void att_phase(float* sm) {
    const int tid = threadIdx.x;
    const int d2  = (tid & 31) * 2;   // packed d-pair
    const int g   = tid >> 5;         // 0..7; rows i = g + 8r, r<7

    u64 eq[7], fq[7], num[7], den[7];
#pragma unroll
    for (int r = 0; r < 7; ++r) {
        const int i  = g + 8 * r;
        const int ii = (i < Nn) ? i : (Nn - 1);
        eq[r]  = *reinterpret_cast<const u64*>(sm + O_EQ + ii * STR + d2);
        fq[r]  = *reinterpret_cast<const u64*>(sm + O_FQ + ii * STR + d2);
        num[r] = 0ull; den[r] = 0ull;
    }
#pragma unroll 2
    for (int j = 0; j < Nn; ++j) {
        const u64 ek = *reinterpret_cast<const u64*>(sm + O_EK + j * STR + d2);
        const u64 fk = *reinterpret_cast<const u64*>(sm + O_FK + j * STR + d2);
        const u64 xv = *reinterpret_cast<const u64*>(sm + O_X  + j * STR + d2);
#pragma unroll
        for (int r = 0; r < 7; ++r) {
            const u64 t1 = mul2(eq[r], ek);
            const u64 t2 = mul2(fq[r], fk);
            const u64 wv = max2(t1, t2);
            den[r] = add2(den[r], wv);
            num[r] = fma2(wv, xv, num[r]);
        }
    }
#pragma unroll
    for (int r = 0; r < 7; ++r) {
        const int i = g + 8 * r;
        if (i < Nn) {
            *reinterpret_cast<u64*>(sm + O_EQ + i * STR + d2) =
                pk2(__fdividef(lo32(num[r]), lo32(den[r])),
                    __fdividef(hi32(num[r]), hi32(den[r])));
        }
    }
}

// ---- copy a 64x64 weight matrix gmem -> smem scratch ------------------------
__device__ __forceinline__ void stage_w(float* sm, const float* __restrict__ W) {
    const int tid = threadIdx.x;
#pragma unroll
    for (int k = 0; k < 4; ++k) {
        const int idx = (tid + k * TPB) * 4;
        *reinterpret_cast<float4*>(sm + O_WS + idx) =
            __ldg(reinterpret_cast<const float4*>(W + idx));
    }
}

// ---- gemm: ATT @ W + b. FINAL=false -> X (av1). FINAL=true -> gmem out ------
template <bool FINAL>
__device__ __forceinline__ void gemm_att(float* sm, int bofs,
                                         const float* __restrict__ emb,
                                         float* __restrict__ out, int b) {
    const int tid  = threadIdx.x;
    const int lane = tid & 31;
    const int w    = tid >> 5;
    const int cg   = w & 3;
    const int rg   = w >> 2;
    const int row  = rg * 32 + lane;
    const int rr   = (row < Nn) ? row : (Nn - 1);
    const int col0 = cg * 16;

    u64 acc[8];
#pragma unroll
    for (int k = 0; k < 8; ++k) acc[k] = 0ull;

    const float* __restrict__ arow = sm + O_EQ + rr * STR;   // ATT lives in EQ
#pragma unroll
    for (int c0 = 0; c0 < Dn; c0 += 8) {
        const float4 xa = *reinterpret_cast<const float4*>(arow + c0);
        const float4 xb = *reinterpret_cast<const float4*>(arow + c0 + 4);
        const float xs[8] = {xa.x, xa.y, xa.z, xa.w, xb.x, xb.y, xb.z, xb.w};
#pragma unroll
        for (int u = 0; u < 8; ++u) {
            const u64 xx = pk2(xs[u], xs[u]);
            const ulonglong2* __restrict__ wp =
                reinterpret_cast<const ulonglong2*>(sm + O_WS + (c0 + u) * Dn + col0);
#pragma unroll
            for (int t = 0; t < 4; ++t) {
                const ulonglong2 W4 = wp[t];
                acc[2 * t]     = fma2(xx, W4.x, acc[2 * t]);
                acc[2 * t + 1] = fma2(xx, W4.y, acc[2 * t + 1]);
            }
        }
    }
    if (row < Nn) {
#pragma unroll
        for (int t = 0; t < 4; ++t) {
            const u64 t0 = add2(acc[2 * t],     *reinterpret_cast<const u64*>(sm + bofs + col0 + 4 * t));
            const u64 t1 = add2(acc[2 * t + 1], *reinterpret_cast<const u64*>(sm + bofs + col0 + 4 * t + 2));
            if (!FINAL) {
                *reinterpret_cast<float4*>(sm + O_X + row * STR + col0 + 4 * t) =
                    make_float4(lo32(t0), hi32(t0), lo32(t1), hi32(t1));
            } else {
                const float4 av = *reinterpret_cast<const float4*>(sm + O_X + row * STR + col0 + 4 * t);
                const float4 e0 = *reinterpret_cast<const float4*>(sm + O_E0 + col0 + 4 * t);
                const float4 ie = __ldg(reinterpret_cast<const float4*>(
                    emb + b * EMB_STRIDE + (row + 1) * Dn + col0 + 4 * t));
                float r0 = lo32(t0) + av.x + e0.x * ie.x;
                float r1 = hi32(t0) + av.y + e0.y * ie.y;
                float r2 = lo32(t1) + av.z + e0.z * ie.z;
                float r3 = hi32(t1) + av.w + e0.w * ie.w;
                r0 = fmaxf(r0, 0.01f * r0); r1 = fmaxf(r1, 0.01f * r1);
                r2 = fmaxf(r2, 0.01f * r2); r3 = fmaxf(r3, 0.01f * r3);
                *reinterpret_cast<float4*>(out + b * (Nn * Dn) + row * Dn + col0 + 4 * t) =
                    make_float4(r0, r1, r2, r3);
            }
        }
    }
}

__global__ void __launch_bounds__(TPB, 2)
att0_fused_kernel(const float* __restrict__ emb,
                  const float* __restrict__ Wa1, const float* __restrict__ ba1,
                  const float* __restrict__ Wa2, const float* __restrict__ ba2,
                  const float* __restrict__ W1,  const float* __restrict__ b1,
                  const float* __restrict__ W2,  const float* __restrict__ b2,
                  float* __restrict__ out) {
    extern __shared__ float sm[];
    const int b   = blockIdx.x;
    const int tid = threadIdx.x;
    const float* __restrict__ eb = emb + b * EMB_STRIDE;

    // load x = i_em (padded stride), Wa1/Wa2, biases, emb0
    for (int idx = tid; idx < Nn * Dn; idx += TPB) {
        sm[O_X + (idx >> 6) * STR + (idx & 63)] = eb[Dn + idx];
    }
    for (int idx = tid; idx < Dn * Dn; idx += TPB) {
        sm[O_WA1 + idx] = Wa1[idx];
        sm[O_WA2 + idx] = Wa2[idx];
    }
    if (tid < Dn) {
        sm[O_BA1 + tid] = ba1[tid];
        sm[O_BA2 + tid] = ba2[tid];
        sm[O_B1  + tid] = b1[tid];
        sm[O_B2  + tid] = b2[tid];
        sm[O_E0  + tid] = eb[tid];
    }
    __syncthreads();

    // ---- layer 1 ----
    qk_phase(sm);                       __syncthreads();
    att_phase(sm);                      __syncthreads();
    stage_w(sm, W1);                    __syncthreads();
    gemm_att<false>(sm, O_B1, emb, out, b); __syncthreads();
    // ---- layer 2 ----
    qk_phase(sm);                       __syncthreads();
    att_phase(sm);                      __syncthreads();
    stage_w(sm, W2);                    __syncthreads();
    gemm_att<true>(sm, O_B2, emb, out, b);
}

extern "C" void kernel_launch(void* const* d_in, const int* in_sizes, int n_in,
                              void* d_out, int out_size) {
    const float* emb = (const float*)d_in[0];
    const float* Wa1 = (const float*)d_in[1];
    const float* ba1 = (const float*)d_in[2];
    const float* Wa2 = (const float*)d_in[3];
    const float* ba2 = (const float*)d_in[4];
    const float* W1  = (const float*)d_in[5];
    const float* b1  = (const float*)d_in[6];
    const float* W2  = (const float*)d_in[7];
    const float* b2  = (const float*)d_in[8];
    float* out = (float*)d_out;

    const size_t smem = SMEM_FLOATS * sizeof(float);   // 102048 B -> 2 CTAs/SM
    cudaFuncSetAttribute(att0_fused_kernel,
                         cudaFuncAttributeMaxDynamicSharedMemorySize, (int)smem);
    att0_fused_kernel<<<Bn, TPB, smem>>>(emb, Wa1, ba1, Wa2, ba2, W1, b1, W2, b2, out);
}

// round 3
// speedup vs baseline: 1.9720x; 1.3226x over previous
#include <cuda_runtime.h>

// ---------------------------------------------------------------------------
// Fully-fused 2-layer GAT attention. 512 CTAs x 256 threads, 3 CTAs/SM.
//  * exp(leaky_relu(q+k)) = max(e^q e^k, e^{.01q} e^{.01k})
//        = Ek * max(Eq, Fq*Gk),  Gk = e^{-0.99k}
//  * value folded: X <- Ek*X (EkX), so att inner loop = 3 fma2 + max.
//  * GEMMs: lane owns packed col-pair, weights per-lane LDG.64 (L1-hit),
//    x rows via uniform LDS broadcast. No weight smem, no padding needed.
// ---------------------------------------------------------------------------

#define TPB 256
typedef unsigned long long u64;

constexpr int Bn = 512, Nn = 50, Dn = 64;
constexpr int ASZ = Nn * Dn;                  // 3200
constexpr int EMB_STRIDE = (Nn + 1) * Dn;     // 3264

// shared layout (floats)
constexpr int O_X  = 0;        // x -> EkX1 -> av1 -> EkX2
constexpr int O_EQ = ASZ;      // Eq -> ATT
constexpr int O_FQ = 2 * ASZ;  // Fq
constexpr int O_EK = 3 * ASZ;  // Ek
constexpr int O_GK = 4 * ASZ;  // Gk = e^{-0.99k}
constexpr int O_BA1 = 5 * ASZ;
constexpr int O_BA2 = O_BA1 + Dn;
constexpr int O_B1  = O_BA2 + Dn;
constexpr int O_B2  = O_B1 + Dn;
constexpr int O_E0  = O_B2 + Dn;
constexpr int SMEM_FLOATS = O_E0 + Dn;        // 16320 floats = 65280 B

// ---- f32x2 helpers --------------------------------------------------------
__device__ __forceinline__ u64 pk2(float lo, float hi) {
    u64 r; asm("mov.b64 %0, {%1,%2};" : "=l"(r) : "f"(lo), "f"(hi)); return r;
}
__device__ __forceinline__ u64 dup2(float x) {
    u64 r; asm("mov.b64 %0, {%1,%1};" : "=l"(r) : "f"(x)); return r;
}
__device__ __forceinline__ float lo32(u64 v) {
    float a, b; asm("mov.b64 {%0,%1}, %2;" : "=f"(a), "=f"(b) : "l"(v)); return a;
}
__device__ __forceinline__ float hi32(u64 v) {
    float a, b; asm("mov.b64 {%0,%1}, %2;" : "=f"(a), "=f"(b) : "l"(v)); return b;
}
__device__ __forceinline__ u64 fma2(u64 a, u64 b, u64 c) {
    u64 d; asm("fma.rn.f32x2 %0, %1, %2, %3;" : "=l"(d) : "l"(a), "l"(b), "l"(c)); return d;
}
__device__ __forceinline__ u64 mul2(u64 a, u64 b) {
    u64 d; asm("mul.rn.f32x2 %0, %1, %2;" : "=l"(d) : "l"(a), "l"(b)); return d;
}
__device__ __forceinline__ u64 max2(u64 a, u64 b) {
    float al, ah, bl, bh;
    asm("mov.b64 {%0,%1}, %2;" : "=f"(al), "=f"(ah) : "l"(a));
    asm("mov.b64 {%0,%1}, %2;" : "=f"(bl), "=f"(bh) : "l"(b));
    return pk2(fmaxf(al, bl), fmaxf(ah, bh));
}

// ---- qk: q = X@Wa1+ba1, k = X@Wa2+ba2 -> Eq,Fq,Ek,Gk; then X <- Ek*X -------
__device__ __forceinline__ void qk_phase(float* sm, const float* __restrict__ Wa1,
                                         const float* __restrict__ Wa2) {
    const int tid = threadIdx.x, lane = tid & 31, w = tid >> 5;
    const int d2 = lane * 2;

    u64 aq[7], ak[7];
    const u64 bq = *reinterpret_cast<const u64*>(sm + O_BA1 + d2);
    const u64 bk = *reinterpret_cast<const u64*>(sm + O_BA2 + d2);
#pragma unroll
    for (int r = 0; r < 7; ++r) { aq[r] = bq; ak[r] = bk; }

#pragma unroll 1
    for (int c0 = 0; c0 < Dn; c0 += 4) {
        float xa[7][4];
#pragma unroll
        for (int r = 0; r < 7; ++r) {
            const float4 v = *reinterpret_cast<const float4*>(sm + O_X + (w + 8 * r) * Dn + c0);
            xa[r][0] = v.x; xa[r][1] = v.y; xa[r][2] = v.z; xa[r][3] = v.w;
        }
#pragma unroll
        for (int u = 0; u < 4; ++u) {
            const u64 wa = __ldg(reinterpret_cast<const u64*>(Wa1 + (c0 + u) * Dn) + lane);
            const u64 wb = __ldg(reinterpret_cast<const u64*>(Wa2 + (c0 + u) * Dn) + lane);
#pragma unroll
            for (int r = 0; r < 7; ++r) {
                const u64 xx = dup2(xa[r][u]);
                aq[r] = fma2(xx, wa, aq[r]);
                ak[r] = fma2(xx, wb, ak[r]);
            }
        }
    }

    u64 ekr[7];
#pragma unroll
    for (int r = 0; r < 7; ++r) {
        const int row = w + 8 * r;
        if (row < Nn) {
            const float qa = lo32(aq[r]), qb = hi32(aq[r]);
            const float ka = lo32(ak[r]), kb = hi32(ak[r]);
            *reinterpret_cast<u64*>(sm + O_EQ + row * Dn + d2) =
                pk2(__expf(qa), __expf(qb));
            *reinterpret_cast<u64*>(sm + O_FQ + row * Dn + d2) =
                pk2(__expf(0.01f * qa), __expf(0.01f * qb));
            ekr[r] = pk2(__expf(ka), __expf(kb));
            *reinterpret_cast<u64*>(sm + O_EK + row * Dn + d2) = ekr[r];
            *reinterpret_cast<u64*>(sm + O_GK + row * Dn + d2) =
                pk2(__expf(-0.99f * ka), __expf(-0.99f * kb));
        }
    }
    __syncthreads();   // all broadcast reads of X done before in-place update
#pragma unroll
    for (int r = 0; r < 7; ++r) {
        const int row = w + 8 * r;
        if (row < Nn) {
            u64* px = reinterpret_cast<u64*>(sm + O_X + row * Dn + d2);
            *px = mul2(ekr[r], *px);               // X <- Ek * X
        }
    }
}

// ---- attention: ATT[i,d] = sum_j m*EkX / sum_j m*Ek, m = max(Eq, Fq*Gk) ----
__device__ __forceinline__ void att_phase(float* sm) {
    const int tid = threadIdx.x;
    const int d2 = (tid & 31) * 2;
    const int g = tid >> 5;

    u64 eq[7], fq[7], num[7], den[7];
#pragma unroll
    for (int r = 0; r < 7; ++r) {
        const int i = g + 8 * r;
        const int ii = (i < Nn) ? i : (Nn - 1);
        eq[r] = *reinterpret_cast<const u64*>(sm + O_EQ + ii * Dn + d2);
        fq[r] = *reinterpret_cast<const u64*>(sm + O_FQ + ii * Dn + d2);
        num[r] = 0ull; den[r] = 0ull;
    }
#pragma unroll 2
    for (int j = 0; j < Nn; ++j) {
        const u64 gk = *reinterpret_cast<const u64*>(sm + O_GK + j * Dn + d2);
        const u64 ek = *reinterpret_cast<const u64*>(sm + O_EK + j * Dn + d2);
        const u64 xw = *reinterpret_cast<const u64*>(sm + O_X  + j * Dn + d2);
#pragma unroll
        for (int r = 0; r < 7; ++r) {
            const u64 m = max2(mul2(fq[r], gk), eq[r]);
            den[r] = fma2(m, ek, den[r]);
            num[r] = fma2(m, xw, num[r]);
        }
    }
#pragma unroll
    for (int r = 0; r < 7; ++r) {
        const int i = g + 8 * r;
        if (i < Nn)
            *reinterpret_cast<u64*>(sm + O_EQ + i * Dn + d2) =
                pk2(__fdividef(lo32(num[r]), lo32(den[r])),
                    __fdividef(hi32(num[r]), hi32(den[r])));
    }
}

// ---- gemm: ATT @ W + b. FINAL=false -> X (av1). FINAL=true -> gmem out -----
template <bool FINAL>
__device__ __forceinline__ void gemm_phase(float* sm, const float* __restrict__ W,
                                           int bofs, const float* __restrict__ emb,
                                           float* __restrict__ out, int b) {
    const int tid = threadIdx.x, lane = tid & 31, w = tid >> 5;
    const int d2 = lane * 2;

    u64 acc[7];
    const u64 bb = *reinterpret_cast<const u64*>(sm + bofs + d2);
#pragma unroll
    for (int r = 0; r < 7; ++r) acc[r] = bb;

#pragma unroll 1
    for (int c0 = 0; c0 < Dn; c0 += 4) {
        float xa[7][4];
#pragma unroll
        for (int r = 0; r < 7; ++r) {
            const float4 v = *reinterpret_cast<const float4*>(sm + O_EQ + (w + 8 * r) * Dn + c0);
            xa[r][0] = v.x; xa[r][1] = v.y; xa[r][2] = v.z; xa[r][3] = v.w;
        }
#pragma unroll
        for (int u = 0; u < 4; ++u) {
            const u64 wv = __ldg(reinterpret_cast<const u64*>(W + (c0 + u) * Dn) + lane);
#pragma unroll
            for (int r = 0; r < 7; ++r)
                acc[r] = fma2(dup2(xa[r][u]), wv, acc[r]);
        }
    }
#pragma unroll
    for (int r = 0; r < 7; ++r) {
        const int row = w + 8 * r;
        if (row < Nn) {
            if (!FINAL) {
                *reinterpret_cast<u64*>(sm + O_X + row * Dn + d2) = acc[r];   // av1
            } else {
                const u64 ekx = *reinterpret_cast<const u64*>(sm + O_X  + row * Dn + d2);
                const u64 ek  = *reinterpret_cast<const u64*>(sm + O_EK + row * Dn + d2);
                const float av0 = __fdividef(lo32(ekx), lo32(ek));   // av1 reconstruct
                const float av1 = __fdividef(hi32(ekx), hi32(ek));
                const float e0a = sm[O_E0 + d2], e0b = sm[O_E0 + d2 + 1];
                const float2 ie = __ldg(reinterpret_cast<const float2*>(
                    emb + b * EMB_STRIDE + (row + 1) * Dn + d2));
                float r0 = lo32(acc[r]) + av0 + e0a * ie.x;
                float r1 = hi32(acc[r]) + av1 + e0b * ie.y;
                r0 = fmaxf(r0, 0.01f * r0);
                r1 = fmaxf(r1, 0.01f * r1);
                *reinterpret_cast<float2*>(out + b * ASZ + row * Dn + d2) =
                    make_float2(r0, r1);
            }
        }
    }
}

__global__ void __launch_bounds__(TPB, 3)
att0_fused_kernel(const float* __restrict__ emb,
                  const float* __restrict__ Wa1, const float* __restrict__ ba1,
                  const float* __restrict__ Wa2, const float* __restrict__ ba2,
                  const float* __restrict__ W1,  const float* __restrict__ b1,
                  const float* __restrict__ W2,  const float* __restrict__ b2,
                  float* __restrict__ out) {
    extern __shared__ float sm[];
    const int b = blockIdx.x, tid = threadIdx.x;
    const float* __restrict__ eb = emb + b * EMB_STRIDE;

    // X = i_em (contiguous copy), biases, emb0
    for (int idx = tid; idx < ASZ / 4; idx += TPB)
        reinterpret_cast<float4*>(sm + O_X)[idx] =
            __ldg(reinterpret_cast<const float4*>(eb + Dn) + idx);
    if (tid < Dn) {
        sm[O_BA1 + tid] = ba1[tid];
        sm[O_BA2 + tid] = ba2[tid];
        sm[O_B1  + tid] = b1[tid];
        sm[O_B2  + tid] = b2[tid];
        sm[O_E0  + tid] = eb[tid];
    }
    __syncthreads();

    // ---- layer 1 ----
    qk_phase(sm, Wa1, Wa2);                        __syncthreads();
    att_phase(sm);                                 __syncthreads();
    gemm_phase<false>(sm, W1, O_B1, emb, out, b);  __syncthreads();
    // ---- layer 2 ----
    qk_phase(sm, Wa1, Wa2);                        __syncthreads();
    att_phase(sm);                                 __syncthreads();
    gemm_phase<true>(sm, W2, O_B2, emb, out, b);
}

extern "C" void kernel_launch(void* const* d_in, const int* in_sizes, int n_in,
                              void* d_out, int out_size) {
    const float* emb = (const float*)d_in[0];
    const float* Wa1 = (const float*)d_in[1];
    const float* ba1 = (const float*)d_in[2];
    const float* Wa2 = (const float*)d_in[3];
    const float* ba2 = (const float*)d_in[4];
    const float* W1  = (const float*)d_in[5];
    const float* b1  = (const float*)d_in[6];
    const float* W2  = (const float*)d_in[7];
    const float* b2  = (const float*)d_in[8];
    float* out = (float*)d_out;

    const size_t smem = SMEM_FLOATS * sizeof(float);   // 65280 B -> 3 CTAs/SM
    cudaFuncSetAttribute(att0_fused_kernel,
                         cudaFuncAttributeMaxDynamicSharedMemorySize, (int)smem);
    att0_fused_kernel<<<Bn, TPB, smem>>>(emb, Wa1, ba1, Wa2, ba2, W1, b1, W2, b2, out);
}

// round 4
// speedup vs baseline: 2.0159x; 1.0222x over previous
#include <cuda_runtime.h>

// ---------------------------------------------------------------------------
// Fully-fused 2-layer GAT attention. 512 CTAs x 256 threads, 4 CTAs/SM
// (single wave on 148 SMs).
//   exp(leaky_relu(q+k)) = Fq * Ek * max(e^{0.99q}, e^{-0.99k}),
//   Fq = e^{0.01q} cancels in softmax => only Hq=e^{0.99q}, Ek, Gk=e^{-0.99k}.
//   Value folded in place: X <- Ek*X.
//   ATT[i] = sum_j max(Hq,Gk)*EkX / sum_j max(Hq,Gk)*Ek
// Packed f32x2 math throughout. EK/GK interleaved for single-LDS.128 fetch.
// ---------------------------------------------------------------------------

#define TPB 256
typedef unsigned long long u64;

constexpr int Bn = 512, Nn = 50, Dn = 64;
constexpr int ASZ = Nn * Dn;                  // 3200
constexpr int EMB_STRIDE = (Nn + 1) * Dn;     // 3264

// shared layout (floats)
constexpr int O_X    = 0;          // x -> EkX1 -> av1 -> EkX2
constexpr int O_HQ   = ASZ;        // Hq -> ATT
constexpr int O_EKGK = 2 * ASZ;    // rows of 128: {ek0,ek1,gk0,gk1} per d-pair
constexpr int O_BA1  = 4 * ASZ;
constexpr int O_BA2  = O_BA1 + Dn;
constexpr int O_B1   = O_BA2 + Dn;
constexpr int O_B2   = O_B1 + Dn;
constexpr int O_E0   = O_B2 + Dn;
constexpr int SMEM_FLOATS = O_E0 + Dn;        // 13120 floats = 52480 B

// ---- f32x2 helpers --------------------------------------------------------
__device__ __forceinline__ u64 pk2(float lo, float hi) {
    u64 r; asm("mov.b64 %0, {%1,%2};" : "=l"(r) : "f"(lo), "f"(hi)); return r;
}
__device__ __forceinline__ u64 dup2(float x) {
    u64 r; asm("mov.b64 %0, {%1,%1};" : "=l"(r) : "f"(x)); return r;
}
__device__ __forceinline__ float lo32(u64 v) {
    float a, b; asm("mov.b64 {%0,%1}, %2;" : "=f"(a), "=f"(b) : "l"(v)); return a;
}
__device__ __forceinline__ float hi32(u64 v) {
    float a, b; asm("mov.b64 {%0,%1}, %2;" : "=f"(a), "=f"(b) : "l"(v)); return b;
}
__device__ __forceinline__ u64 fma2(u64 a, u64 b, u64 c) {
    u64 d; asm("fma.rn.f32x2 %0, %1, %2, %3;" : "=l"(d) : "l"(a), "l"(b), "l"(c)); return d;
}
__device__ __forceinline__ u64 mul2(u64 a, u64 b) {
    u64 d; asm("mul.rn.f32x2 %0, %1, %2;" : "=l"(d) : "l"(a), "l"(b)); return d;
}
__device__ __forceinline__ u64 max2(u64 a, u64 b) {
    float al, ah, bl, bh;
    asm("mov.b64 {%0,%1}, %2;" : "=f"(al), "=f"(ah) : "l"(a));
    asm("mov.b64 {%0,%1}, %2;" : "=f"(bl), "=f"(bh) : "l"(b));
    return pk2(fmaxf(al, bl), fmaxf(ah, bh));
}

// ---- qk: q=X@Wa1+ba1, k=X@Wa2+ba2 -> HQ, EK|GK; then X <- Ek*X -------------
__device__ __forceinline__ void qk_phase(float* sm, const float* __restrict__ Wa1,
                                         const float* __restrict__ Wa2) {
    const int tid = threadIdx.x, lane = tid & 31, w = tid >> 5;
    const int d2 = lane * 2;

    u64 aq[7], ak[7];
    const u64 bq = *reinterpret_cast<const u64*>(sm + O_BA1 + d2);
    const u64 bk = *reinterpret_cast<const u64*>(sm + O_BA2 + d2);
#pragma unroll
    for (int r = 0; r < 7; ++r) { aq[r] = bq; ak[r] = bk; }

#pragma unroll 1
    for (int c0 = 0; c0 < Dn; c0 += 2) {
        u64 x2[7];
#pragma unroll
        for (int r = 0; r < 7; ++r)
            x2[r] = *reinterpret_cast<const u64*>(sm + O_X + (w + 8 * r) * Dn + c0);
#pragma unroll
        for (int u = 0; u < 2; ++u) {
            const u64 wa = __ldg(reinterpret_cast<const u64*>(Wa1 + (c0 + u) * Dn) + lane);
            const u64 wb = __ldg(reinterpret_cast<const u64*>(Wa2 + (c0 + u) * Dn) + lane);
#pragma unroll
            for (int r = 0; r < 7; ++r) {
                const u64 xx = dup2(u ? hi32(x2[r]) : lo32(x2[r]));
                aq[r] = fma2(xx, wa, aq[r]);
                ak[r] = fma2(xx, wb, ak[r]);
            }
        }
    }

    u64 ekr[7];
#pragma unroll
    for (int r = 0; r < 7; ++r) {
        const int row = w + 8 * r;
        if (row < Nn) {
            const float qa = lo32(aq[r]), qb = hi32(aq[r]);
            const float ka = lo32(ak[r]), kb = hi32(ak[r]);
            *reinterpret_cast<u64*>(sm + O_HQ + row * Dn + d2) =
                pk2(__expf(0.99f * qa), __expf(0.99f * qb));
            const float e0 = __expf(ka), e1 = __expf(kb);
            ekr[r] = pk2(e0, e1);
            *reinterpret_cast<float4*>(sm + O_EKGK + row * 2 * Dn + d2 * 2) =
                make_float4(e0, e1, __expf(-0.99f * ka), __expf(-0.99f * kb));
        }
    }
    __syncwarp();   // rows are warp-private: only intra-warp read/write hazard on X
#pragma unroll
    for (int r = 0; r < 7; ++r) {
        const int row = w + 8 * r;
        if (row < Nn) {
            u64* px = reinterpret_cast<u64*>(sm + O_X + row * Dn + d2);
            *px = mul2(ekr[r], *px);   // X <- Ek * X
        }
    }
}

// ---- attention ------------------------------------------------------------
__device__ __forceinline__ void att_phase(float* sm) {
    const int tid = threadIdx.x;
    const int d2 = (tid & 31) * 2;
    const int g = tid >> 5;

    u64 hq[7], num[7], den[7];
#pragma unroll
    for (int r = 0; r < 7; ++r) {
        const int i = g + 8 * r;
        const int ii = (i < Nn) ? i : (Nn - 1);
        hq[r] = *reinterpret_cast<const u64*>(sm + O_HQ + ii * Dn + d2);
        num[r] = 0ull; den[r] = 0ull;
    }
#pragma unroll 2
    for (int j = 0; j < Nn; ++j) {
        const float4 eg = *reinterpret_cast<const float4*>(sm + O_EKGK + j * 2 * Dn + d2 * 2);
        const u64 ek = pk2(eg.x, eg.y);
        const u64 gk = pk2(eg.z, eg.w);
        const u64 xw = *reinterpret_cast<const u64*>(sm + O_X + j * Dn + d2);
#pragma unroll
        for (int r = 0; r < 7; ++r) {
            const u64 m = max2(hq[r], gk);
            den[r] = fma2(m, ek, den[r]);
            num[r] = fma2(m, xw, num[r]);
        }
    }
#pragma unroll
    for (int r = 0; r < 7; ++r) {
        const int i = g + 8 * r;
        if (i < Nn)
            *reinterpret_cast<u64*>(sm + O_HQ + i * Dn + d2) =
                pk2(__fdividef(lo32(num[r]), lo32(den[r])),
                    __fdividef(hi32(num[r]), hi32(den[r])));
    }
}

// ---- gemm: ATT @ W + b. FINAL=false -> X (av1). FINAL=true -> gmem out -----
template <bool FINAL>
__device__ __forceinline__ void gemm_phase(float* sm, const float* __restrict__ W,
                                           int bofs, const float* __restrict__ emb,
                                           float* __restrict__ out, int b) {
    const int tid = threadIdx.x, lane = tid & 31, w = tid >> 5;
    const int d2 = lane * 2;

    u64 acc[7];
    const u64 bb = *reinterpret_cast<const u64*>(sm + bofs + d2);
#pragma unroll
    for (int r = 0; r < 7; ++r) acc[r] = bb;

#pragma unroll 1
    for (int c0 = 0; c0 < Dn; c0 += 4) {
        float xa[7][4];
#pragma unroll
        for (int r = 0; r < 7; ++r) {
            const float4 v = *reinterpret_cast<const float4*>(sm + O_HQ + (w + 8 * r) * Dn + c0);
            xa[r][0] = v.x; xa[r][1] = v.y; xa[r][2] = v.z; xa[r][3] = v.w;
        }
#pragma unroll
        for (int u = 0; u < 4; ++u) {
            const u64 wv = __ldg(reinterpret_cast<const u64*>(W + (c0 + u) * Dn) + lane);
#pragma unroll
            for (int r = 0; r < 7; ++r)
                acc[r] = fma2(dup2(xa[r][u]), wv, acc[r]);
        }
    }
#pragma unroll
    for (int r = 0; r < 7; ++r) {
        const int row = w + 8 * r;
        if (row < Nn) {
            if (!FINAL) {
                *reinterpret_cast<u64*>(sm + O_X + row * Dn + d2) = acc[r];   // av1
            } else {
                const u64 ekx = *reinterpret_cast<const u64*>(sm + O_X + row * Dn + d2);
                const u64 ek  = *reinterpret_cast<const u64*>(sm + O_EKGK + row * 2 * Dn + d2 * 2);
                const float av0 = __fdividef(lo32(ekx), lo32(ek));   // av1 = EkX/Ek
                const float av1 = __fdividef(hi32(ekx), hi32(ek));
                const float e0a = sm[O_E0 + d2], e0b = sm[O_E0 + d2 + 1];
                const float2 ie = __ldg(reinterpret_cast<const float2*>(
                    emb + b * EMB_STRIDE + (row + 1) * Dn + d2));
                float r0 = lo32(acc[r]) + av0 + e0a * ie.x;
                float r1 = hi32(acc[r]) + av1 + e0b * ie.y;
                r0 = fmaxf(r0, 0.01f * r0);
                r1 = fmaxf(r1, 0.01f * r1);
                *reinterpret_cast<float2*>(out + b * ASZ + row * Dn + d2) =
                    make_float2(r0, r1);
            }
        }
    }
}

__global__ void __launch_bounds__(TPB, 4)
att0_fused_kernel(const float* __restrict__ emb,
                  const float* __restrict__ Wa1, const float* __restrict__ ba1,
                  const float* __restrict__ Wa2, const float* __restrict__ ba2,
                  const float* __restrict__ W1,  const float* __restrict__ b1,
                  const float* __restrict__ W2,  const float* __restrict__ b2,
                  float* __restrict__ out) {
    extern __shared__ float sm[];
    const int b = blockIdx.x, tid = threadIdx.x;
    const float* __restrict__ eb = emb + b * EMB_STRIDE;

    for (int idx = tid; idx < ASZ / 4; idx += TPB)
        reinterpret_cast<float4*>(sm + O_X)[idx] =
            __ldg(reinterpret_cast<const float4*>(eb + Dn) + idx);
    if (tid < Dn) {
        sm[O_BA1 + tid] = ba1[tid];
        sm[O_BA2 + tid] = ba2[tid];
        sm[O_B1  + tid] = b1[tid];
        sm[O_B2  + tid] = b2[tid];
        sm[O_E0  + tid] = eb[tid];
    }
    __syncthreads();

    // ---- layer 1 ----
    qk_phase(sm, Wa1, Wa2);                        __syncthreads();
    att_phase(sm);                                 __syncthreads();
    gemm_phase<false>(sm, W1, O_B1, emb, out, b);  __syncthreads();
    // ---- layer 2 ----
    qk_phase(sm, Wa1, Wa2);                        __syncthreads();
    att_phase(sm);                                 __syncthreads();
    gemm_phase<true>(sm, W2, O_B2, emb, out, b);
}

extern "C" void kernel_launch(void* const* d_in, const int* in_sizes, int n_in,
                              void* d_out, int out_size) {
    const float* emb = (const float*)d_in[0];
    const float* Wa1 = (const float*)d_in[1];
    const float* ba1 = (const float*)d_in[2];
    const float* Wa2 = (const float*)d_in[3];
    const float* ba2 = (const float*)d_in[4];
    const float* W1  = (const float*)d_in[5];
    const float* b1  = (const float*)d_in[6];
    const float* W2  = (const float*)d_in[7];
    const float* b2  = (const float*)d_in[8];
    float* out = (float*)d_out;

    const size_t smem = SMEM_FLOATS * sizeof(float);   // 52480 B -> 4 CTAs/SM
    cudaFuncSetAttribute(att0_fused_kernel,
                         cudaFuncAttributeMaxDynamicSharedMemorySize, (int)smem);
    att0_fused_kernel<<<Bn, TPB, smem>>>(emb, Wa1, ba1, Wa2, ba2, W1, b1, W2, b2, out);
}